// round 1
// baseline (speedup 1.0000x reference)
#include <cuda_runtime.h>
#include <math.h>

#define BB 8
#define SS 2048
#define DD 64
#define HH 4
#define HD 16
#define FF (HH*HD)          // 64
#define NROWS (BB*SS)       // 16384
#define QBLK 128
#define KBLK 128

// scratch (no allocations allowed)
__device__ float g_Q[BB*HH*SS*HD];   // [B,H,S,HD]
__device__ float g_K[BB*HH*SS*HD];
__device__ float g_V[BB*HH*SS*HD];
__device__ float g_att[NROWS*FF];    // [B,S,H*HD] (concat layout)

__device__ __forceinline__ float ex2(float x) {
    float r;
    asm("ex2.approx.ftz.f32 %0, %1;" : "=f"(r) : "f"(x));
    return r;
}

// ---------------- QKV projection ----------------
// 256 threads = 4 row-lanes x 64 features; 64 rows per block.
__global__ __launch_bounds__(256) void proj_kernel(
    const float* __restrict__ data,
    const float* __restrict__ Wq,
    const float* __restrict__ Wk,
    const float* __restrict__ Wv)
{
    __shared__ float sWq[DD*FF];  // stored as [d][f], f = h*16+e
    __shared__ float sWk[DD*FF];
    __shared__ float sWv[DD*FF];

    const int tid = threadIdx.x;
    for (int i = tid; i < DD*FF; i += 256) {
        int d = i >> 6, f = i & 63;
        int h = f >> 4, e = f & 15;
        int src = (h*DD + d)*HD + e;
        sWq[i] = Wq[src];
        sWk[i] = Wk[src];
        sWv[i] = Wv[src];
    }
    __syncthreads();

    const int f = tid & 63;
    const int h = f >> 4, e = f & 15;
    const int rowSub = tid >> 6;        // 0..3
    const int rowBase = blockIdx.x * 64;

    for (int r = rowSub; r < 64; r += 4) {
        int row = rowBase + r;          // global row = b*S + s
        const float* __restrict__ x = data + row * DD;
        float aq = 0.f, ak = 0.f, av = 0.f;
        #pragma unroll 8
        for (int d = 0; d < DD; d++) {
            float xv = x[d];            // broadcast within warp
            aq += xv * sWq[d*FF + f];
            ak += xv * sWk[d*FF + f];
            av += xv * sWv[d*FF + f];
        }
        int b = row / SS, s = row % SS;
        int dst = (((b*HH + h)*SS) + s)*HD + e;
        g_Q[dst] = aq;
        g_K[dst] = ak;
        g_V[dst] = av;
    }
}

// ---------------- flash attention ----------------
// grid = (S/QBLK, B*H); 1 thread = 1 query row; K/V tiles in smem.
__global__ __launch_bounds__(QBLK) void attn_kernel()
{
    const int bh  = blockIdx.y;                 // b*H + h
    const int tid = threadIdx.x;
    const int qrow = blockIdx.x * QBLK + tid;   // 0..S-1

    __shared__ float sK[KBLK*HD];
    __shared__ float sV[KBLK*HD];

    // fold softmax scale and log2(e) into q
    const float c = (1.4426950408889634f) * rsqrtf((float)HD);
    float q[HD];
    const float* __restrict__ Qp = g_Q + ((size_t)bh*SS + qrow)*HD;
    #pragma unroll
    for (int e = 0; e < HD; e++) q[e] = Qp[e] * c;

    float m = -INFINITY, l = 0.f;
    float o[HD];
    #pragma unroll
    for (int e = 0; e < HD; e++) o[e] = 0.f;

    const float* __restrict__ Kbase = g_K + (size_t)bh*SS*HD;
    const float* __restrict__ Vbase = g_V + (size_t)bh*SS*HD;

    for (int kt = 0; kt < SS/KBLK; kt++) {
        __syncthreads();
        const float* __restrict__ Kp = Kbase + kt*KBLK*HD;
        const float* __restrict__ Vp = Vbase + kt*KBLK*HD;
        #pragma unroll
        for (int i = tid; i < KBLK*HD; i += QBLK) {
            sK[i] = Kp[i];
            sV[i] = Vp[i];
        }
        __syncthreads();

        #pragma unroll 4
        for (int j = 0; j < KBLK; j++) {
            const float* kr = &sK[j*HD];
            float s0 = 0.f, s1 = 0.f, s2 = 0.f, s3 = 0.f;
            #pragma unroll
            for (int e = 0; e < HD; e += 4) {
                s0 += q[e+0] * kr[e+0];
                s1 += q[e+1] * kr[e+1];
                s2 += q[e+2] * kr[e+2];
                s3 += q[e+3] * kr[e+3];
            }
            float s = (s0 + s1) + (s2 + s3);   // log2-domain score
            if (s > m) {
                float corr = ex2(m - s);       // 0 on first key (m=-inf)
                l *= corr;
                #pragma unroll
                for (int e = 0; e < HD; e++) o[e] *= corr;
                m = s;
            }
            float p = ex2(s - m);
            l += p;
            const float* vr = &sV[j*HD];
            #pragma unroll
            for (int e = 0; e < HD; e++) o[e] += p * vr[e];
        }
    }

    const float inv = 1.f / l;
    const int b = bh / HH, h = bh % HH;
    float* __restrict__ op = g_att + ((size_t)b*SS + qrow)*FF + h*HD;
    #pragma unroll
    for (int e = 0; e < HD; e++) op[e] = o[e] * inv;
}

// ---------------- output projection ----------------
// y[n,do] = sum_f att[n,f] * Wo[do,f] + bo[do]
__global__ __launch_bounds__(256) void outproj_kernel(
    const float* __restrict__ Wo,
    const float* __restrict__ bo,
    float* __restrict__ out)
{
    __shared__ float sWo[FF*DD];   // transposed: sWo[f*64 + do] = Wo[do*64 + f]
    __shared__ float sbo[DD];

    const int tid = threadIdx.x;
    for (int i = tid; i < FF*DD; i += 256) {
        int f = i >> 6, dout = i & 63;
        sWo[i] = Wo[dout*FF + f];
    }
    if (tid < DD) sbo[tid] = bo[tid];
    __syncthreads();

    const int dout = tid & 63;
    const int rowSub = tid >> 6;
    const int rowBase = blockIdx.x * 64;

    for (int r = rowSub; r < 64; r += 4) {
        int row = rowBase + r;
        const float* __restrict__ x = g_att + (size_t)row * FF;
        float acc = sbo[dout];
        #pragma unroll 8
        for (int f = 0; f < FF; f++) {
            acc += x[f] * sWo[f*DD + dout];
        }
        out[(size_t)row * DD + dout] = acc;
    }
}

extern "C" void kernel_launch(void* const* d_in, const int* in_sizes, int n_in,
                              void* d_out, int out_size)
{
    const float* data = (const float*)d_in[0];
    const float* Wq   = (const float*)d_in[1];
    const float* Wk   = (const float*)d_in[2];
    const float* Wv   = (const float*)d_in[3];
    const float* Wo   = (const float*)d_in[4];
    const float* bo   = (const float*)d_in[5];
    float* out = (float*)d_out;

    proj_kernel<<<NROWS/64, 256>>>(data, Wq, Wk, Wv);
    attn_kernel<<<dim3(SS/QBLK, BB*HH), QBLK>>>();
    outproj_kernel<<<NROWS/64, 256>>>(Wo, bo, out);
}

// round 2
// speedup vs baseline: 1.0387x; 1.0387x over previous
#include <cuda_runtime.h>
#include <math.h>

#define BB 8
#define SS 2048
#define DD 64
#define HH 4
#define HD 16
#define FF (HH*HD)          // 64
#define NROWS (BB*SS)       // 16384
#define QBLK 128
#define KBLK 128

typedef unsigned long long u64;

// scratch (no allocations allowed)
__device__ float g_Q[BB*HH*SS*HD];   // [B,H,S,HD], pre-scaled by log2e/sqrt(HD)
__device__ float g_K[BB*HH*SS*HD];
__device__ float g_V[BB*HH*SS*HD];
__device__ float g_att[NROWS*FF];    // [B,S,H*HD] (concat layout)

__device__ __forceinline__ float ex2(float x) {
    float r;
    asm("ex2.approx.ftz.f32 %0, %1;" : "=f"(r) : "f"(x));
    return r;
}
__device__ __forceinline__ u64 fma2(u64 a, u64 b, u64 c) {
    u64 d;
    asm("fma.rn.f32x2 %0, %1, %2, %3;" : "=l"(d) : "l"(a), "l"(b), "l"(c));
    return d;
}
__device__ __forceinline__ u64 add2(u64 a, u64 b) {
    u64 d;
    asm("add.rn.f32x2 %0, %1, %2;" : "=l"(d) : "l"(a), "l"(b));
    return d;
}
__device__ __forceinline__ u64 mul2(u64 a, u64 b) {
    u64 d;
    asm("mul.rn.f32x2 %0, %1, %2;" : "=l"(d) : "l"(a), "l"(b));
    return d;
}
__device__ __forceinline__ u64 pack2(float lo, float hi) {
    u64 d;
    asm("mov.b64 %0, {%1, %2};" : "=l"(d) : "f"(lo), "f"(hi));
    return d;
}
__device__ __forceinline__ void unpack2(u64 a, float& lo, float& hi) {
    asm("mov.b64 {%0, %1}, %2;" : "=f"(lo), "=f"(hi) : "l"(a));
}

// ---------------- QKV projection ----------------
// 256 threads: lane f = tid&63 owns one feature column; 4 row-groups;
// each thread computes 4 rows at once so every weight LDS feeds 12 FMAs.
__global__ __launch_bounds__(256) void proj_kernel(
    const float* __restrict__ data,
    const float* __restrict__ Wq,
    const float* __restrict__ Wk,
    const float* __restrict__ Wv)
{
    __shared__ float sWq[DD*FF];  // [d][f], f = h*16+e; lanes hit consecutive banks
    __shared__ float sWk[DD*FF];
    __shared__ float sWv[DD*FF];

    const int tid = threadIdx.x;
    const float c = 1.4426950408889634f * rsqrtf((float)HD); // log2e / sqrt(HD)
    for (int i = tid; i < DD*FF; i += 256) {
        int d = i >> 6, f = i & 63;
        int h = f >> 4, e = f & 15;
        int src = (h*DD + d)*HD + e;
        sWq[i] = Wq[src] * c;   // fold softmax scale into Q
        sWk[i] = Wk[src];
        sWv[i] = Wv[src];
    }
    __syncthreads();

    const int f = tid & 63;
    const int h = f >> 4, e = f & 15;
    const int g = tid >> 6;             // 0..3
    const int rowBase = blockIdx.x * 64;

    for (int it = 0; it < 4; it++) {
        int row0 = rowBase + g*4 + it*16;    // 4 consecutive rows
        const float4* __restrict__ x0 = (const float4*)(data + (size_t)(row0+0)*DD);
        const float4* __restrict__ x1 = (const float4*)(data + (size_t)(row0+1)*DD);
        const float4* __restrict__ x2 = (const float4*)(data + (size_t)(row0+2)*DD);
        const float4* __restrict__ x3 = (const float4*)(data + (size_t)(row0+3)*DD);

        float aq[4] = {0,0,0,0}, ak[4] = {0,0,0,0}, av[4] = {0,0,0,0};
        #pragma unroll
        for (int d4 = 0; d4 < DD/4; d4++) {
            float4 v0 = x0[d4], v1 = x1[d4], v2 = x2[d4], v3 = x3[d4];
            float xs[4][4] = {{v0.x,v1.x,v2.x,v3.x},{v0.y,v1.y,v2.y,v3.y},
                              {v0.z,v1.z,v2.z,v3.z},{v0.w,v1.w,v2.w,v3.w}};
            #pragma unroll
            for (int dd = 0; dd < 4; dd++) {
                int d = d4*4 + dd;
                float wq = sWq[d*FF + f], wk = sWk[d*FF + f], wv = sWv[d*FF + f];
                #pragma unroll
                for (int r = 0; r < 4; r++) {
                    aq[r] += xs[dd][r] * wq;
                    ak[r] += xs[dd][r] * wk;
                    av[r] += xs[dd][r] * wv;
                }
            }
        }
        #pragma unroll
        for (int r = 0; r < 4; r++) {
            int row = row0 + r;
            int b = row / SS, s = row % SS;
            int dst = (((b*HH + h)*SS) + s)*HD + e;
            g_Q[dst] = aq[r];
            g_K[dst] = ak[r];
            g_V[dst] = av[r];
        }
    }
}

// ---------------- flash attention (packed f32x2) ----------------
// grid = (S/QBLK, B*H); 1 thread = 1 query row; K/V tiles in smem.
__global__ __launch_bounds__(QBLK) void attn_kernel()
{
    const int bh  = blockIdx.y;                 // b*H + h
    const int tid = threadIdx.x;
    const int qrow = blockIdx.x * QBLK + tid;   // 0..S-1

    __shared__ alignas(16) float sK[KBLK*HD];
    __shared__ alignas(16) float sV[KBLK*HD];

    // q pre-scaled by log2e/sqrt(HD) in proj; pack into 8 f32x2
    u64 qp[HD/2];
    {
        const float4* __restrict__ Qp = (const float4*)(g_Q + ((size_t)bh*SS + qrow)*HD);
        #pragma unroll
        for (int i = 0; i < HD/4; i++) {
            float4 v = Qp[i];
            qp[i*2+0] = pack2(v.x, v.y);
            qp[i*2+1] = pack2(v.z, v.w);
        }
    }

    float m = -INFINITY, l = 0.f;
    u64 op[HD/2];
    #pragma unroll
    for (int i = 0; i < HD/2; i++) op[i] = 0ull;

    const float4* __restrict__ Kbase = (const float4*)(g_K + (size_t)bh*SS*HD);
    const float4* __restrict__ Vbase = (const float4*)(g_V + (size_t)bh*SS*HD);
    float4* sK4 = (float4*)sK;
    float4* sV4 = (float4*)sV;
    const u64* sK64 = (const u64*)sK;
    const u64* sV64 = (const u64*)sV;

    for (int kt = 0; kt < SS/KBLK; kt++) {
        __syncthreads();
        const float4* __restrict__ Kp = Kbase + kt*(KBLK*HD/4);
        const float4* __restrict__ Vp = Vbase + kt*(KBLK*HD/4);
        #pragma unroll
        for (int i = tid; i < KBLK*HD/4; i += QBLK) {
            sK4[i] = Kp[i];
            sV4[i] = Vp[i];
        }
        __syncthreads();

        #pragma unroll 2
        for (int j = 0; j < KBLK; j++) {
            const u64* kr = sK64 + j*(HD/2);
            // score dot: 8 packed FMAs over 2 chains
            u64 a0 = fma2(qp[0], kr[0], 0ull);
            u64 a1 = fma2(qp[1], kr[1], 0ull);
            a0 = fma2(qp[2], kr[2], a0);
            a1 = fma2(qp[3], kr[3], a1);
            a0 = fma2(qp[4], kr[4], a0);
            a1 = fma2(qp[5], kr[5], a1);
            a0 = fma2(qp[6], kr[6], a0);
            a1 = fma2(qp[7], kr[7], a1);
            a0 = add2(a0, a1);
            float slo, shi;
            unpack2(a0, slo, shi);
            float s = slo + shi;               // log2-domain score

            if (s > m) {
                float corr = ex2(m - s);       // 0 on first key (m=-inf)
                l *= corr;
                u64 corrp = pack2(corr, corr);
                #pragma unroll
                for (int i = 0; i < HD/2; i++) op[i] = mul2(op[i], corrp);
                m = s;
            }
            float p = ex2(s - m);
            l += p;
            u64 pp = pack2(p, p);
            const u64* vr = sV64 + j*(HD/2);
            #pragma unroll
            for (int i = 0; i < HD/2; i++) op[i] = fma2(pp, vr[i], op[i]);
        }
    }

    const float inv = 1.f / l;
    const int b = bh / HH, h = bh % HH;
    float* __restrict__ outp = g_att + ((size_t)b*SS + qrow)*FF + h*HD;
    #pragma unroll
    for (int i = 0; i < HD/2; i++) {
        float lo, hi;
        unpack2(op[i], lo, hi);
        outp[i*2+0] = lo * inv;
        outp[i*2+1] = hi * inv;
    }
}

// ---------------- output projection ----------------
// y[n,do] = sum_f att[n,f] * Wo[do,f] + bo[do]; 4 rows per thread
__global__ __launch_bounds__(256) void outproj_kernel(
    const float* __restrict__ Wo,
    const float* __restrict__ bo,
    float* __restrict__ out)
{
    __shared__ float sWo[FF*DD];   // transposed: sWo[f*64 + do] = Wo[do*64 + f]
    __shared__ float sbo[DD];

    const int tid = threadIdx.x;
    for (int i = tid; i < FF*DD; i += 256) {
        int f = i >> 6, dout = i & 63;
        sWo[i] = Wo[dout*FF + f];
    }
    if (tid < DD) sbo[tid] = bo[tid];
    __syncthreads();

    const int dout = tid & 63;
    const int g = tid >> 6;
    const int rowBase = blockIdx.x * 64;
    const float bias = sbo[dout];

    for (int it = 0; it < 4; it++) {
        int row0 = rowBase + g*4 + it*16;
        const float4* __restrict__ x0 = (const float4*)(g_att + (size_t)(row0+0)*FF);
        const float4* __restrict__ x1 = (const float4*)(g_att + (size_t)(row0+1)*FF);
        const float4* __restrict__ x2 = (const float4*)(g_att + (size_t)(row0+2)*FF);
        const float4* __restrict__ x3 = (const float4*)(g_att + (size_t)(row0+3)*FF);

        float acc[4] = {bias, bias, bias, bias};
        #pragma unroll
        for (int f4 = 0; f4 < FF/4; f4++) {
            float4 v0 = x0[f4], v1 = x1[f4], v2 = x2[f4], v3 = x3[f4];
            float xs[4][4] = {{v0.x,v1.x,v2.x,v3.x},{v0.y,v1.y,v2.y,v3.y},
                              {v0.z,v1.z,v2.z,v3.z},{v0.w,v1.w,v2.w,v3.w}};
            #pragma unroll
            for (int ff = 0; ff < 4; ff++) {
                float w = sWo[(f4*4+ff)*DD + dout];
                #pragma unroll
                for (int r = 0; r < 4; r++) acc[r] += xs[ff][r] * w;
            }
        }
        #pragma unroll
        for (int r = 0; r < 4; r++)
            out[(size_t)(row0+r)*DD + dout] = acc[r];
    }
}

extern "C" void kernel_launch(void* const* d_in, const int* in_sizes, int n_in,
                              void* d_out, int out_size)
{
    const float* data = (const float*)d_in[0];
    const float* Wq   = (const float*)d_in[1];
    const float* Wk   = (const float*)d_in[2];
    const float* Wv   = (const float*)d_in[3];
    const float* Wo   = (const float*)d_in[4];
    const float* bo   = (const float*)d_in[5];
    float* out = (float*)d_out;

    proj_kernel<<<NROWS/64, 256>>>(data, Wq, Wk, Wv);
    attn_kernel<<<dim3(SS/QBLK, BB*HH), QBLK>>>();
    outproj_kernel<<<NROWS/64, 256>>>(Wo, bo, out);
}